// round 15
// baseline (speedup 1.0000x reference)
#include <cuda_runtime.h>
#include <cuda_fp16.h>
#include <cstdint>
#include <math.h>

// Problem constants
#define NROWS 1024
#define DDIM  512
#define NCLS  70722
#define NT    185            // ceil(NCLS/384)
#define CPAD  (NT*384)       // 71040
#define PADC  (CPAD - NCLS)  // 318 zero padding classes (logit exactly 0)
#define M_MARGIN 0.4f
#define H_SCALE  0.333f
#define S_SCALE  64.0f
#define EPS_M    0.001f
#define PI_F     3.14159265358979f
#define LOG2E64  92.332482616893f   // 64 * log2(e)

// GEMM tiling (f16, HMMA m16n8k16, f16 accumulate)
#define BM 128
#define BN 384
#define BK 32                 // f16 elements per k-tile
#define PAD 8
#define ROWH (BK + PAD)       // 40 halfs per smem row
#define NKT (DDIM/BK)         // 16
#define NSTG 4
#define NWARP_N 6

// dynamic smem layout (bytes)
#define A_ST   (BM*ROWH*2)            // 10240 per stage
#define B_ST   (BN*ROWH*2)            // 30720 per stage
#define SB_OFF (NSTG*A_ST)            // 40960
#define SMAX_OFF (SB_OFF + NSTG*B_ST) // 163840
#define SSUM_OFF (SMAX_OFF + NWARP_N*BM*4)  // +3072
#define SMEM_TOTAL (SSUM_OFF + NWARP_N*BM*4)// 169984

// ---------------- device scratch (static: no allocations) ----------------
__device__ __half g_A[NROWS*DDIM];               // normalized x, f16
__device__ __half g_W[(size_t)CPAD*DDIM];        // normalized weights, f16 (~72.7MB)
__device__ float g_xnorm[NROWS];
__device__ float g_gang[NROWS];
__device__ float g_gadd[NROWS];
__device__ float g_pmax[(size_t)NROWS*NT];
__device__ float g_psum[(size_t)NROWS*NT];
__device__ float g_lab_plain[NROWS];
__device__ float g_lab_adj[NROWS];
__device__ float g_loss[NROWS];

// ---------------- helpers ----------------
__device__ __forceinline__ float warpReduceSum(float v) {
#pragma unroll
    for (int o = 16; o > 0; o >>= 1) v += __shfl_xor_sync(0xffffffffu, v, o);
    return v;
}
__device__ __forceinline__ uint32_t smem_u32(const void* p) {
    return (uint32_t)__cvta_generic_to_shared(p);
}
__device__ __forceinline__ void cp16(uint32_t s, const void* g) {
    asm volatile("cp.async.cg.shared.global [%0], [%1], 16;\n" :: "r"(s), "l"(g));
}
__device__ __forceinline__ void lse_combine(float& m, float& s, float om, float os) {
    float nm = fmaxf(m, om);
    s = s * __expf(m - nm) + os * __expf(om - nm);
    m = nm;
}
__device__ __forceinline__ __half2 ex2_h2(__half2 a) {
    uint32_t au = *(uint32_t*)&a, ru;
    asm("ex2.approx.f16x2 %0, %1;" : "=r"(ru) : "r"(au));
    return *(__half2*)&ru;
}
__device__ __forceinline__ void ldmx4(uint32_t addr, uint32_t* r) {
    asm volatile("ldmatrix.sync.aligned.m8n8.x4.shared.b16 {%0,%1,%2,%3}, [%4];"
                 : "=r"(r[0]), "=r"(r[1]), "=r"(r[2]), "=r"(r[3]) : "r"(addr));
}

// ---------------- prep kernels ----------------
__global__ void prep_x_kernel(const float* __restrict__ x) {
    int row = blockIdx.x, tid = threadIdx.x;          // 128 threads
    const float4* xr = (const float4*)(x + (size_t)row * DDIM);
    float4 v = xr[tid];
    float s = v.x*v.x + v.y*v.y + v.z*v.z + v.w*v.w;
    __shared__ float red[4];
    s = warpReduceSum(s);
    if ((tid & 31) == 0) red[tid >> 5] = s;
    __syncthreads();
    float tot = red[0] + red[1] + red[2] + red[3];
    float nrm = sqrtf(tot);
    if (tid == 0) g_xnorm[row] = nrm;
    float inv = 1.0f / fmaxf(nrm, 1e-12f);
    __half2 h0 = __floats2half2_rn(v.x*inv, v.y*inv);
    __half2 h1 = __floats2half2_rn(v.z*inv, v.w*inv);
    uint2 pk; pk.x = *(unsigned*)&h0; pk.y = *(unsigned*)&h1;
    ((uint2*)g_A)[(size_t)row * (DDIM/4) + tid] = pk;
}

// warp-per-row: 256 threads = 8 warps = 8 rows per block, shuffle-only reduction
__global__ void prep_w_kernel(const float* __restrict__ w) {
    int warp = threadIdx.x >> 5, lane = threadIdx.x & 31;
    int row = blockIdx.x * 8 + warp;                  // grid = CPAD/8 blocks
    uint2* dst = ((uint2*)g_W) + (size_t)row * (DDIM/4);
    if (row < NCLS) {
        const float4* wr = (const float4*)(w + (size_t)row * DDIM);
        float4 v[4];
        float ss = 0.0f;
#pragma unroll
        for (int i = 0; i < 4; i++) {
            v[i] = wr[lane + 32*i];
            ss += v[i].x*v[i].x + v[i].y*v[i].y + v[i].z*v[i].z + v[i].w*v[i].w;
        }
        ss = warpReduceSum(ss);                        // all lanes hold the sum
        float inv = 1.0f / fmaxf(sqrtf(ss), 1e-12f);
#pragma unroll
        for (int i = 0; i < 4; i++) {
            __half2 h0 = __floats2half2_rn(v[i].x*inv, v[i].y*inv);
            __half2 h1 = __floats2half2_rn(v[i].z*inv, v[i].w*inv);
            uint2 pk; pk.x = *(unsigned*)&h0; pk.y = *(unsigned*)&h1;
            dst[lane + 32*i] = pk;
        }
    } else {
        uint2 z; z.x = 0u; z.y = 0u;                   // zero rows -> logit exactly 0
#pragma unroll
        for (int i = 0; i < 4; i++) dst[lane + 32*i] = z;
    }
}

__global__ void stats_kernel() {
    int tid = threadIdx.x;                            // 1024 threads
    float n = g_xnorm[tid];
    float s = fminf(fmaxf(fmaxf(n, 1e-8f), 0.001f), 100.0f);
    __shared__ float red[32];
    float t = warpReduceSum(s);
    if ((tid & 31) == 0) red[tid >> 5] = t;
    __syncthreads();
    if (tid < 32) { float v = red[tid]; v = warpReduceSum(v); if (tid == 0) red[0] = v; }
    __syncthreads();
    float mean = red[0] / (float)NROWS;
    float d = s - mean;
    __syncthreads();
    t = warpReduceSum(d * d);
    if ((tid & 31) == 0) red[tid >> 5] = t;
    __syncthreads();
    if (tid < 32) { float v = red[tid]; v = warpReduceSum(v); if (tid == 0) red[0] = v; }
    __syncthreads();
    float stdv = sqrtf(red[0] / (float)(NROWS - 1));   // ddof=1
    float ms = fminf(fmaxf(d / (stdv + EPS_M) * H_SCALE, -1.0f), 1.0f);
    g_gang[tid] = -M_MARGIN * ms;
    g_gadd[tid] = M_MARGIN + M_MARGIN * ms;
}

// warp-per-row label kernel: 128 blocks x 8 warps, shuffle-only
__global__ void label_kernel(const float* __restrict__ x,
                             const int* __restrict__ labels,
                             const float* __restrict__ w) {
    int warp = threadIdx.x >> 5, lane = threadIdx.x & 31;
    int i = blockIdx.x * 8 + warp;                    // grid = 128 blocks
    int l = labels[i];
    l = max(0, min(l, NCLS - 1));                     // safety clamp
    const float4* xr = (const float4*)(x + (size_t)i * DDIM);
    const float4* wr = (const float4*)(w + (size_t)l * DDIM);
    float dot = 0.0f, wsq = 0.0f;
#pragma unroll
    for (int k = 0; k < 4; k++) {
        float4 a = xr[lane + 32*k], b = wr[lane + 32*k];
        dot += a.x*b.x + a.y*b.y + a.z*b.z + a.w*b.w;
        wsq += b.x*b.x + b.y*b.y + b.z*b.z + b.w*b.w;
    }
    dot = warpReduceSum(dot);
    wsq = warpReduceSum(wsq);
    if (lane == 0) {
        float xn = fmaxf(g_xnorm[i], 1e-12f);
        float wn = fmaxf(sqrtf(wsq), 1e-12f);
        float c  = fminf(fmaxf(dot / (xn * wn), -1.0f), 1.0f);
        float th = acosf(c);
        float plain = S_SCALE * cosf(fminf(fmaxf(th, EPS_M), PI_F - EPS_M));
        float thm = fminf(fmaxf(th + g_gang[i], EPS_M), PI_F - EPS_M);
        float adj = S_SCALE * (cosf(thm) - g_gadd[i]);
        g_lab_plain[i] = plain;
        g_lab_adj[i]   = adj;
    }
}

// ---------------- main fused f16 GEMM (f16 accumulate) + online LSE ----------------
// CTA tile 128x384, warp tile 64x64 (12 warps: 2m x 6n), 1 CTA/SM
// Rotated loop: barrier + next-tile frag loads sit UNDER the final MMA burst
__global__ void __launch_bounds__(384, 1) gemm_lse_kernel() {
    extern __shared__ __align__(16) char smem[];
    uint32_t sb = smem_u32(smem);
    float* sMax = (float*)(smem + SMAX_OFF);   // [NWARP_N][BM]
    float* sSum = (float*)(smem + SSUM_OFF);   // [NWARP_N][BM]

    int mt = blockIdx.x, ct = blockIdx.y;
    int tid = threadIdx.x;
    int lane = tid & 31, warp = tid >> 5;
    int wm = warp & 1;        // 0..1 -> m offset (64 each)
    int wn = warp >> 1;       // 0..5 -> n offset (64 each)

    const int m0 = mt * BM;
    const int n0 = ct * BN;

    // f16 accumulators: [mi=4][ni=8][2 halves-pairs]
    uint32_t acc[4][8][2];
#pragma unroll
    for (int i = 0; i < 4; i++)
#pragma unroll
        for (int j = 0; j < 8; j++) { acc[i][j][0] = 0u; acc[i][j][1] = 0u; }

    // loaders: B: 384 threads x 4 x16B; A: threads 0..255 x 2 x16B
    int ar = tid >> 2;            // 0..95
    int ac = (tid & 3) * 8;       // 0,8,16,24 (f16 elements)
    const __half* gA = g_A + (size_t)(m0 + ar) * DDIM + ac;   // valid rows for tid<256
    const __half* gB = g_W + (size_t)(n0 + ar) * DDIM + ac;

#define LOAD_TILE(stg, kt) do {                                                   \
        int _k0 = (kt) * BK;                                                      \
        uint32_t _b = sb + SB_OFF + (stg) * B_ST + (ar * ROWH + ac) * 2;          \
        cp16(_b,                  gB + _k0);                                      \
        cp16(_b + 96*ROWH*2,      gB + (size_t)96*DDIM  + _k0);                   \
        cp16(_b + 192*ROWH*2,     gB + (size_t)192*DDIM + _k0);                   \
        cp16(_b + 288*ROWH*2,     gB + (size_t)288*DDIM + _k0);                   \
        if (tid < 256) {                                                          \
            uint32_t _a = sb + (stg) * A_ST + (ar * ROWH + ac) * 2;               \
            cp16(_a,              gA + _k0);                                      \
            cp16(_a + 64*ROWH*2,  gA + (size_t)64*DDIM  + _k0);                   \
        }                                                                         \
        asm volatile("cp.async.commit_group;\n" ::);                              \
    } while (0)

    // fragment loaders for (stage, kk): A 4 x4-ldmatrix, B 4 x4-ldmatrix
    int arow0 = wm * 64 + (lane & 15);       // A base row (+16 per mi)
    int brow0 = wn * 64 + (lane & 15);       // B base row (+16 per nj-pair)
#define LD_FRAGS(stg, kk, fa, fb) do {                                            \
        int _kb = (kk) * 16 + (lane >> 4) * 8;                                    \
        uint32_t _ab = sb + (stg) * A_ST + _kb * 2;                               \
        uint32_t _bb = sb + SB_OFF + (stg) * B_ST + _kb * 2;                      \
        ldmx4(_ab + (arow0      ) * ROWH * 2, (fa)[0]);                           \
        ldmx4(_ab + (arow0 + 16 ) * ROWH * 2, (fa)[1]);                           \
        ldmx4(_ab + (arow0 + 32 ) * ROWH * 2, (fa)[2]);                           \
        ldmx4(_ab + (arow0 + 48 ) * ROWH * 2, (fa)[3]);                           \
        uint32_t _t[4];                                                           \
        ldmx4(_bb + (brow0      ) * ROWH * 2, _t);                                \
        (fb)[0][0]=_t[0]; (fb)[1][0]=_t[1]; (fb)[0][1]=_t[2]; (fb)[1][1]=_t[3];   \
        ldmx4(_bb + (brow0 + 16 ) * ROWH * 2, _t);                                \
        (fb)[2][0]=_t[0]; (fb)[3][0]=_t[1]; (fb)[2][1]=_t[2]; (fb)[3][1]=_t[3];   \
        ldmx4(_bb + (brow0 + 32 ) * ROWH * 2, _t);                                \
        (fb)[4][0]=_t[0]; (fb)[5][0]=_t[1]; (fb)[4][1]=_t[2]; (fb)[5][1]=_t[3];   \
        ldmx4(_bb + (brow0 + 48 ) * ROWH * 2, _t);                                \
        (fb)[6][0]=_t[0]; (fb)[7][0]=_t[1]; (fb)[6][1]=_t[2]; (fb)[7][1]=_t[3];   \
    } while (0)

#define MMA_SET(fa, fb) do {                                                      \
        _Pragma("unroll")                                                         \
        for (int mi = 0; mi < 4; mi++)                                            \
            _Pragma("unroll")                                                     \
            for (int ni = 0; ni < 8; ni++) {                                      \
                asm volatile(                                                     \
                    "mma.sync.aligned.m16n8k16.row.col.f16.f16.f16.f16 "          \
                    "{%0,%1}, {%2,%3,%4,%5}, {%6,%7}, {%0,%1};"                   \
                    : "+r"(acc[mi][ni][0]), "+r"(acc[mi][ni][1])                  \
                    : "r"((fa)[mi][0]), "r"((fa)[mi][1]),                         \
                      "r"((fa)[mi][2]), "r"((fa)[mi][3]),                         \
                      "r"((fb)[ni][0]), "r"((fb)[ni][1]));                        \
            }                                                                     \
    } while (0)

    // double-buffered fragments
    uint32_t fA0[4][4], fB0[8][2], fA1[4][4], fB1[8][2];

    LOAD_TILE(0, 0);
    LOAD_TILE(1, 1);
    LOAD_TILE(2, 2);
    asm volatile("cp.async.wait_group 2;\n" ::: "memory");
    __syncthreads();
    LD_FRAGS(0, 0, fA0, fB0);

    for (int kt = 0; kt < NKT; kt++) {
        int s = kt & 3;
        LD_FRAGS(s, 1, fA1, fB1);          // kk=1 frags issue under kk=0 MMAs
        MMA_SET(fA0, fB0);
        if (kt + 3 < NKT) LOAD_TILE((kt + 3) & 3, kt + 3);
        else asm volatile("cp.async.commit_group;\n" ::);
        asm volatile("cp.async.wait_group 2;\n" ::: "memory");
        __syncthreads();
        if (kt + 1 < NKT) { LD_FRAGS((kt + 1) & 3, 0, fA0, fB0); }  // under fB1 MMAs
        MMA_SET(fA1, fB1);
    }
#undef LOAD_TILE
#undef LD_FRAGS
#undef MMA_SET

    // ---- epilogue: packed f16x2 clamp -> max -> ex2.f16x2 -> sum ----
    const __half2 h2hi = __float2half2_rn(1.0f);
    const __half2 h2lo = __float2half2_rn(-1.0f);
    const __half2 k2   = __float2half2_rn(LOG2E64);
#pragma unroll
    for (int mi = 0; mi < 4; mi++) {
#pragma unroll
        for (int hf = 0; hf < 2; hf++) {            // hf selects row group (+8)
            int rw = wm*64 + mi*16 + hf*8 + (lane >> 2);     // row within CTA
            __half2 v[8];
#pragma unroll
            for (int ni = 0; ni < 8; ni++) {
                __half2 c2 = *(__half2*)&acc[mi][ni][hf];
                v[ni] = __hmin2(__hmax2(c2, h2lo), h2hi);
            }
            __half2 m01 = __hmax2(v[0], v[1]), m23 = __hmax2(v[2], v[3]);
            __half2 m45 = __hmax2(v[4], v[5]), m67 = __hmax2(v[6], v[7]);
            __half2 m03 = __hmax2(m01, m23),   m47 = __hmax2(m45, m67);
            __half2 m2  = __hmax2(m03, m47);
            float mx = fmaxf(__low2float(m2), __high2float(m2));
            mx = fmaxf(mx, __shfl_xor_sync(0xffffffffu, mx, 1));
            mx = fmaxf(mx, __shfl_xor_sync(0xffffffffu, mx, 2));
            __half2 noff = __float2half2_rn(-LOG2E64 * mx);
            __half2 e[8];
#pragma unroll
            for (int ni = 0; ni < 8; ni++)
                e[ni] = ex2_h2(__hfma2(v[ni], k2, noff));
            __half2 s01 = __hadd2(e[0], e[1]), s23 = __hadd2(e[2], e[3]);
            __half2 s45 = __hadd2(e[4], e[5]), s67 = __hadd2(e[6], e[7]);
            __half2 s03 = __hadd2(s01, s23),   s47 = __hadd2(s45, s67);
            __half2 st  = __hadd2(s03, s47);
            float s = __low2float(st) + __high2float(st);
            s += __shfl_xor_sync(0xffffffffu, s, 1);
            s += __shfl_xor_sync(0xffffffffu, s, 2);
            if ((lane & 3) == 0) { sMax[wn*BM + rw] = S_SCALE * mx; sSum[wn*BM + rw] = s; }
        }
    }
    __syncthreads();

    if (tid < BM) {
        float m = sMax[tid], s = sSum[tid];
#pragma unroll
        for (int wq = 1; wq < NWARP_N; wq++)
            lse_combine(m, s, sMax[wq*BM + tid], sSum[wq*BM + tid]);
        int grow = m0 + tid;
        g_pmax[(size_t)grow * NT + ct] = m;
        g_psum[(size_t)grow * NT + ct] = s;
    }
}

// ---------------- final reductions ----------------
__global__ void reduce1_kernel() {
    int row = blockIdx.x, tid = threadIdx.x;   // 128 threads
    float mx = -1e30f, sm = 0.0f;
    for (int t = tid; t < NT; t += 128) {
        float m = g_pmax[(size_t)row * NT + t];
        float s = g_psum[(size_t)row * NT + t];
        lse_combine(mx, sm, m, s);
    }
#pragma unroll
    for (int o = 16; o > 0; o >>= 1) {
        float om = __shfl_xor_sync(0xffffffffu, mx, o);
        float os = __shfl_xor_sync(0xffffffffu, sm, o);
        lse_combine(mx, sm, om, os);
    }
    __shared__ float rm[4], rs[4];
    int lane = tid & 31, w = tid >> 5;
    if (lane == 0) { rm[w] = mx; rs[w] = sm; }
    __syncthreads();
    if (tid == 0) {
        float m = rm[0], s = rs[0];
        lse_combine(m, s, rm[1], rs[1]);
        lse_combine(m, s, rm[2], rs[2]);
        lse_combine(m, s, rm[3], rs[3]);
        // remove PADC padding terms (logit exactly 0), swap plain->adjusted label term
        float plain = g_lab_plain[row], adj = g_lab_adj[row];
        float s2 = s - (float)PADC * __expf(0.0f - m) - __expf(plain - m) + __expf(adj - m);
        float lse = m + __logf(s2);
        g_loss[row] = lse - adj;
    }
}

__global__ void reduce2_kernel(float* __restrict__ out) {
    int tid = threadIdx.x;    // 256 threads
    float s = 0.0f;
    for (int t = tid; t < NROWS; t += 256) s += g_loss[t];
    s = warpReduceSum(s);
    __shared__ float red[8];
    if ((tid & 31) == 0) red[tid >> 5] = s;
    __syncthreads();
    if (tid == 0) {
        float tot = 0.0f;
        for (int i = 0; i < 8; i++) tot += red[i];
        out[0] = tot / (float)NROWS;
    }
}

// ---------------- launch ----------------
extern "C" void kernel_launch(void* const* d_in, const int* in_sizes, int n_in,
                              void* d_out, int out_size) {
    const float* x      = (const float*)d_in[0];
    const int*   labels = (const int*)d_in[1];
    const float* w      = (const float*)d_in[2];
    float* out = (float*)d_out;

    cudaFuncSetAttribute(gemm_lse_kernel, cudaFuncAttributeMaxDynamicSharedMemorySize, SMEM_TOTAL);

    // order chosen so the GEMM sits at the ncu capture slot
    prep_x_kernel<<<NROWS, 128>>>(x);
    prep_w_kernel<<<CPAD/8, 256>>>(w);
    stats_kernel<<<1, 1024>>>();
    gemm_lse_kernel<<<dim3(8, NT), 384, SMEM_TOTAL>>>();
    label_kernel<<<NROWS/8, 256>>>(x, labels, w);
    reduce1_kernel<<<NROWS, 128>>>();
    reduce2_kernel<<<1, 256>>>(out);
}

// round 16
// speedup vs baseline: 1.1203x; 1.1203x over previous
#include <cuda_runtime.h>
#include <cuda_fp16.h>
#include <cstdint>
#include <math.h>

// Problem constants
#define NROWS 1024
#define DDIM  512
#define NCLS  70722
#define NT    185            // ceil(NCLS/384)
#define CPAD  (NT*384)       // 71040
#define PADC  (CPAD - NCLS)  // 318 zero padding classes (logit exactly 0)
#define M_MARGIN 0.4f
#define H_SCALE  0.333f
#define S_SCALE  64.0f
#define EPS_M    0.001f
#define PI_F     3.14159265358979f
#define LOG2E64  92.332482616893f   // 64 * log2(e)

// GEMM tiling (f16, HMMA m16n8k16, f16 accumulate) — round-14 proven config
#define BM 128
#define BN 384
#define BK 32                 // f16 elements per k-tile
#define PAD 8
#define ROWH (BK + PAD)       // 40 halfs per smem row
#define NKT (DDIM/BK)         // 16
#define NSTG 4
#define NWARP_N 6

// dynamic smem layout (bytes)
#define A_ST   (BM*ROWH*2)            // 10240 per stage
#define B_ST   (BN*ROWH*2)            // 30720 per stage
#define SB_OFF (NSTG*A_ST)            // 40960
#define SMAX_OFF (SB_OFF + NSTG*B_ST) // 163840
#define SSUM_OFF (SMAX_OFF + NWARP_N*BM*4)  // +3072
#define SMEM_TOTAL (SSUM_OFF + NWARP_N*BM*4)// 169984

// ---------------- device scratch (static: no allocations) ----------------
__device__ __half g_A[NROWS*DDIM];               // normalized x, f16
__device__ __half g_W[(size_t)CPAD*DDIM];        // normalized weights, f16 (~72.7MB)
__device__ float g_xnorm[NROWS];
__device__ float g_gang[NROWS];
__device__ float g_gadd[NROWS];
__device__ float g_pmax[(size_t)NROWS*NT];
__device__ float g_psum[(size_t)NROWS*NT];
__device__ float g_loss[NROWS];

// ---------------- helpers ----------------
__device__ __forceinline__ float warpReduceSum(float v) {
#pragma unroll
    for (int o = 16; o > 0; o >>= 1) v += __shfl_xor_sync(0xffffffffu, v, o);
    return v;
}
__device__ __forceinline__ uint32_t smem_u32(const void* p) {
    return (uint32_t)__cvta_generic_to_shared(p);
}
__device__ __forceinline__ void cp16(uint32_t s, const void* g) {
    asm volatile("cp.async.cg.shared.global [%0], [%1], 16;\n" :: "r"(s), "l"(g));
}
__device__ __forceinline__ void lse_combine(float& m, float& s, float om, float os) {
    float nm = fmaxf(m, om);
    s = s * __expf(m - nm) + os * __expf(om - nm);
    m = nm;
}
__device__ __forceinline__ __half2 ex2_h2(__half2 a) {
    uint32_t au = *(uint32_t*)&a, ru;
    asm("ex2.approx.f16x2 %0, %1;" : "=r"(ru) : "r"(au));
    return *(__half2*)&ru;
}
__device__ __forceinline__ void ldmx4(uint32_t addr, uint32_t* r) {
    asm volatile("ldmatrix.sync.aligned.m8n8.x4.shared.b16 {%0,%1,%2,%3}, [%4];"
                 : "=r"(r[0]), "=r"(r[1]), "=r"(r[2]), "=r"(r[3]) : "r"(addr));
}

// ---------------- prep kernels ----------------
__global__ void prep_x_kernel(const float* __restrict__ x) {
    int row = blockIdx.x, tid = threadIdx.x;          // 128 threads
    const float4* xr = (const float4*)(x + (size_t)row * DDIM);
    float4 v = xr[tid];
    float s = v.x*v.x + v.y*v.y + v.z*v.z + v.w*v.w;
    __shared__ float red[4];
    s = warpReduceSum(s);
    if ((tid & 31) == 0) red[tid >> 5] = s;
    __syncthreads();
    float tot = red[0] + red[1] + red[2] + red[3];
    float nrm = sqrtf(tot);
    if (tid == 0) g_xnorm[row] = nrm;
    float inv = 1.0f / fmaxf(nrm, 1e-12f);
    __half2 h0 = __floats2half2_rn(v.x*inv, v.y*inv);
    __half2 h1 = __floats2half2_rn(v.z*inv, v.w*inv);
    uint2 pk; pk.x = *(unsigned*)&h0; pk.y = *(unsigned*)&h1;
    ((uint2*)g_A)[(size_t)row * (DDIM/4) + tid] = pk;
}

// warp-per-row: 256 threads = 8 warps = 8 rows per block, shuffle-only reduction
__global__ void prep_w_kernel(const float* __restrict__ w) {
    int warp = threadIdx.x >> 5, lane = threadIdx.x & 31;
    int row = blockIdx.x * 8 + warp;                  // grid = CPAD/8 blocks
    uint2* dst = ((uint2*)g_W) + (size_t)row * (DDIM/4);
    if (row < NCLS) {
        const float4* wr = (const float4*)(w + (size_t)row * DDIM);
        float4 v[4];
        float ss = 0.0f;
#pragma unroll
        for (int i = 0; i < 4; i++) {
            v[i] = wr[lane + 32*i];
            ss += v[i].x*v[i].x + v[i].y*v[i].y + v[i].z*v[i].z + v[i].w*v[i].w;
        }
        ss = warpReduceSum(ss);                        // all lanes hold the sum
        float inv = 1.0f / fmaxf(sqrtf(ss), 1e-12f);
#pragma unroll
        for (int i = 0; i < 4; i++) {
            __half2 h0 = __floats2half2_rn(v[i].x*inv, v[i].y*inv);
            __half2 h1 = __floats2half2_rn(v[i].z*inv, v[i].w*inv);
            uint2 pk; pk.x = *(unsigned*)&h0; pk.y = *(unsigned*)&h1;
            dst[lane + 32*i] = pk;
        }
    } else {
        uint2 z; z.x = 0u; z.y = 0u;                   // zero rows -> logit exactly 0
#pragma unroll
        for (int i = 0; i < 4; i++) dst[lane + 32*i] = z;
    }
}

__global__ void stats_kernel() {
    int tid = threadIdx.x;                            // 1024 threads
    float n = g_xnorm[tid];
    float s = fminf(fmaxf(fmaxf(n, 1e-8f), 0.001f), 100.0f);
    __shared__ float red[32];
    float t = warpReduceSum(s);
    if ((tid & 31) == 0) red[tid >> 5] = t;
    __syncthreads();
    if (tid < 32) { float v = red[tid]; v = warpReduceSum(v); if (tid == 0) red[0] = v; }
    __syncthreads();
    float mean = red[0] / (float)NROWS;
    float d = s - mean;
    __syncthreads();
    t = warpReduceSum(d * d);
    if ((tid & 31) == 0) red[tid >> 5] = t;
    __syncthreads();
    if (tid < 32) { float v = red[tid]; v = warpReduceSum(v); if (tid == 0) red[0] = v; }
    __syncthreads();
    float stdv = sqrtf(red[0] / (float)(NROWS - 1));   // ddof=1
    float ms = fminf(fmaxf(d / (stdv + EPS_M) * H_SCALE, -1.0f), 1.0f);
    g_gang[tid] = -M_MARGIN * ms;
    g_gadd[tid] = M_MARGIN + M_MARGIN * ms;
}

// ---------------- main fused f16 GEMM (f16 accumulate) + online LSE ----------------
// CTA tile 128x384, warp tile 64x64 (12 warps: 2m x 6n), 1 CTA/SM — round-14 verbatim
__global__ void __launch_bounds__(384, 1) gemm_lse_kernel() {
    extern __shared__ __align__(16) char smem[];
    uint32_t sb = smem_u32(smem);
    float* sMax = (float*)(smem + SMAX_OFF);   // [NWARP_N][BM]
    float* sSum = (float*)(smem + SSUM_OFF);   // [NWARP_N][BM]

    int mt = blockIdx.x, ct = blockIdx.y;
    int tid = threadIdx.x;
    int lane = tid & 31, warp = tid >> 5;
    int wm = warp & 1;        // 0..1 -> m offset (64 each)
    int wn = warp >> 1;       // 0..5 -> n offset (64 each)

    const int m0 = mt * BM;
    const int n0 = ct * BN;

    // f16 accumulators: [mi=4][ni=8][2 halves-pairs]
    uint32_t acc[4][8][2];
#pragma unroll
    for (int i = 0; i < 4; i++)
#pragma unroll
        for (int j = 0; j < 8; j++) { acc[i][j][0] = 0u; acc[i][j][1] = 0u; }

    // loaders: B: 384 threads x 4 x16B; A: threads 0..255 x 2 x16B
    int ar = tid >> 2;            // 0..95
    int ac = (tid & 3) * 8;       // 0,8,16,24 (f16 elements)
    const __half* gA = g_A + (size_t)(m0 + ar) * DDIM + ac;   // valid rows for tid<256
    const __half* gB = g_W + (size_t)(n0 + ar) * DDIM + ac;

#define LOAD_TILE(stg, kt) do {                                                   \
        int _k0 = (kt) * BK;                                                      \
        uint32_t _b = sb + SB_OFF + (stg) * B_ST + (ar * ROWH + ac) * 2;          \
        cp16(_b,                  gB + _k0);                                      \
        cp16(_b + 96*ROWH*2,      gB + (size_t)96*DDIM  + _k0);                   \
        cp16(_b + 192*ROWH*2,     gB + (size_t)192*DDIM + _k0);                   \
        cp16(_b + 288*ROWH*2,     gB + (size_t)288*DDIM + _k0);                   \
        if (tid < 256) {                                                          \
            uint32_t _a = sb + (stg) * A_ST + (ar * ROWH + ac) * 2;               \
            cp16(_a,              gA + _k0);                                      \
            cp16(_a + 64*ROWH*2,  gA + (size_t)64*DDIM  + _k0);                   \
        }                                                                         \
        asm volatile("cp.async.commit_group;\n" ::);                              \
    } while (0)

    // fragment loaders for (stage, kk): A 4 x4-ldmatrix, B 4 x4-ldmatrix
    int arow0 = wm * 64 + (lane & 15);       // A base row (+16 per mi)
    int brow0 = wn * 64 + (lane & 15);       // B base row (+16 per nj-pair)
#define LD_FRAGS(stg, kk, fa, fb) do {                                            \
        int _kb = (kk) * 16 + (lane >> 4) * 8;                                    \
        uint32_t _ab = sb + (stg) * A_ST + _kb * 2;                               \
        uint32_t _bb = sb + SB_OFF + (stg) * B_ST + _kb * 2;                      \
        ldmx4(_ab + (arow0      ) * ROWH * 2, (fa)[0]);                           \
        ldmx4(_ab + (arow0 + 16 ) * ROWH * 2, (fa)[1]);                           \
        ldmx4(_ab + (arow0 + 32 ) * ROWH * 2, (fa)[2]);                           \
        ldmx4(_ab + (arow0 + 48 ) * ROWH * 2, (fa)[3]);                           \
        uint32_t _t[4];                                                           \
        ldmx4(_bb + (brow0      ) * ROWH * 2, _t);                                \
        (fb)[0][0]=_t[0]; (fb)[1][0]=_t[1]; (fb)[0][1]=_t[2]; (fb)[1][1]=_t[3];   \
        ldmx4(_bb + (brow0 + 16 ) * ROWH * 2, _t);                                \
        (fb)[2][0]=_t[0]; (fb)[3][0]=_t[1]; (fb)[2][1]=_t[2]; (fb)[3][1]=_t[3];   \
        ldmx4(_bb + (brow0 + 32 ) * ROWH * 2, _t);                                \
        (fb)[4][0]=_t[0]; (fb)[5][0]=_t[1]; (fb)[4][1]=_t[2]; (fb)[5][1]=_t[3];   \
        ldmx4(_bb + (brow0 + 48 ) * ROWH * 2, _t);                                \
        (fb)[6][0]=_t[0]; (fb)[7][0]=_t[1]; (fb)[6][1]=_t[2]; (fb)[7][1]=_t[3];   \
    } while (0)

#define MMA_SET(fa, fb) do {                                                      \
        _Pragma("unroll")                                                         \
        for (int mi = 0; mi < 4; mi++)                                            \
            _Pragma("unroll")                                                     \
            for (int ni = 0; ni < 8; ni++) {                                      \
                asm volatile(                                                     \
                    "mma.sync.aligned.m16n8k16.row.col.f16.f16.f16.f16 "          \
                    "{%0,%1}, {%2,%3,%4,%5}, {%6,%7}, {%0,%1};"                   \
                    : "+r"(acc[mi][ni][0]), "+r"(acc[mi][ni][1])                  \
                    : "r"((fa)[mi][0]), "r"((fa)[mi][1]),                         \
                      "r"((fa)[mi][2]), "r"((fa)[mi][3]),                         \
                      "r"((fb)[ni][0]), "r"((fb)[ni][1]));                        \
            }                                                                     \
    } while (0)

    // double-buffered fragments
    uint32_t fA0[4][4], fB0[8][2], fA1[4][4], fB1[8][2];

    LOAD_TILE(0, 0);
    LOAD_TILE(1, 1);
    LOAD_TILE(2, 2);
    asm volatile("cp.async.wait_group 2;\n" ::: "memory");
    __syncthreads();
    LD_FRAGS(0, 0, fA0, fB0);

    for (int kt = 0; kt < NKT; kt++) {
        int s = kt & 3;
        LD_FRAGS(s, 1, fA1, fB1);          // kk=1 frags issue under kk=0 MMAs
        MMA_SET(fA0, fB0);
        if (kt + 3 < NKT) LOAD_TILE((kt + 3) & 3, kt + 3);
        else asm volatile("cp.async.commit_group;\n" ::);
        MMA_SET(fA1, fB1);
        asm volatile("cp.async.wait_group 2;\n" ::: "memory");
        __syncthreads();
        if (kt + 1 < NKT) { LD_FRAGS((kt + 1) & 3, 0, fA0, fB0); }
    }
#undef LOAD_TILE
#undef LD_FRAGS
#undef MMA_SET

    // ---- epilogue: packed f16x2 clamp -> max -> ex2.f16x2 -> sum ----
    const __half2 h2hi = __float2half2_rn(1.0f);
    const __half2 h2lo = __float2half2_rn(-1.0f);
    const __half2 k2   = __float2half2_rn(LOG2E64);
#pragma unroll
    for (int mi = 0; mi < 4; mi++) {
#pragma unroll
        for (int hf = 0; hf < 2; hf++) {            // hf selects row group (+8)
            int rw = wm*64 + mi*16 + hf*8 + (lane >> 2);     // row within CTA
            __half2 v[8];
#pragma unroll
            for (int ni = 0; ni < 8; ni++) {
                __half2 c2 = *(__half2*)&acc[mi][ni][hf];
                v[ni] = __hmin2(__hmax2(c2, h2lo), h2hi);
            }
            __half2 m01 = __hmax2(v[0], v[1]), m23 = __hmax2(v[2], v[3]);
            __half2 m45 = __hmax2(v[4], v[5]), m67 = __hmax2(v[6], v[7]);
            __half2 m03 = __hmax2(m01, m23),   m47 = __hmax2(m45, m67);
            __half2 m2  = __hmax2(m03, m47);
            float mx = fmaxf(__low2float(m2), __high2float(m2));
            mx = fmaxf(mx, __shfl_xor_sync(0xffffffffu, mx, 1));
            mx = fmaxf(mx, __shfl_xor_sync(0xffffffffu, mx, 2));
            __half2 noff = __float2half2_rn(-LOG2E64 * mx);
            __half2 e[8];
#pragma unroll
            for (int ni = 0; ni < 8; ni++)
                e[ni] = ex2_h2(__hfma2(v[ni], k2, noff));
            __half2 s01 = __hadd2(e[0], e[1]), s23 = __hadd2(e[2], e[3]);
            __half2 s45 = __hadd2(e[4], e[5]), s67 = __hadd2(e[6], e[7]);
            __half2 s03 = __hadd2(s01, s23),   s47 = __hadd2(s45, s67);
            __half2 st  = __hadd2(s03, s47);
            float s = __low2float(st) + __high2float(st);
            s += __shfl_xor_sync(0xffffffffu, s, 1);
            s += __shfl_xor_sync(0xffffffffu, s, 2);
            if ((lane & 3) == 0) { sMax[wn*BM + rw] = S_SCALE * mx; sSum[wn*BM + rw] = s; }
        }
    }
    __syncthreads();

    if (tid < BM) {
        float m = sMax[tid], s = sSum[tid];
#pragma unroll
        for (int wq = 1; wq < NWARP_N; wq++)
            lse_combine(m, s, sMax[wq*BM + tid], sSum[wq*BM + tid]);
        int grow = m0 + tid;
        g_pmax[(size_t)grow * NT + ct] = m;
        g_psum[(size_t)grow * NT + ct] = s;
    }
}

// ---------------- final reductions (label math fused in) ----------------
__global__ void reduce1_kernel(const float* __restrict__ x,
                               const int* __restrict__ labels,
                               const float* __restrict__ w) {
    int row = blockIdx.x, tid = threadIdx.x;   // 128 threads
    __shared__ float rd[4], rw4[4];
    __shared__ float sPlain, sAdj;

    // ---- fused label-logit computation (exact fp32) ----
    int l = labels[row];
    l = max(0, min(l, NCLS - 1));              // safety clamp
    {
        const float4* xr = (const float4*)(x + (size_t)row * DDIM);
        const float4* wr = (const float4*)(w + (size_t)l * DDIM);
        float4 a = xr[tid], b = wr[tid];
        float dot = a.x*b.x + a.y*b.y + a.z*b.z + a.w*b.w;
        float wsq = b.x*b.x + b.y*b.y + b.z*b.z + b.w*b.w;
        dot = warpReduceSum(dot);
        wsq = warpReduceSum(wsq);
        if ((tid & 31) == 0) { rd[tid >> 5] = dot; rw4[tid >> 5] = wsq; }
    }
    __syncthreads();
    if (tid == 0) {
        float Dv = rd[0] + rd[1] + rd[2] + rd[3];
        float Wv = rw4[0] + rw4[1] + rw4[2] + rw4[3];
        float xn = fmaxf(g_xnorm[row], 1e-12f);
        float wn = fmaxf(sqrtf(Wv), 1e-12f);
        float c  = fminf(fmaxf(Dv / (xn * wn), -1.0f), 1.0f);
        float th = acosf(c);
        sPlain = S_SCALE * cosf(fminf(fmaxf(th, EPS_M), PI_F - EPS_M));
        float thm = fminf(fmaxf(th + g_gang[row], EPS_M), PI_F - EPS_M);
        sAdj = S_SCALE * (cosf(thm) - g_gadd[row]);
    }

    // ---- LSE partial combine ----
    float mx = -1e30f, sm = 0.0f;
    for (int t = tid; t < NT; t += 128) {
        float m = g_pmax[(size_t)row * NT + t];
        float s = g_psum[(size_t)row * NT + t];
        lse_combine(mx, sm, m, s);
    }
#pragma unroll
    for (int o = 16; o > 0; o >>= 1) {
        float om = __shfl_xor_sync(0xffffffffu, mx, o);
        float os = __shfl_xor_sync(0xffffffffu, sm, o);
        lse_combine(mx, sm, om, os);
    }
    __shared__ float rm[4], rs[4];
    int lane = tid & 31, wp = tid >> 5;
    if (lane == 0) { rm[wp] = mx; rs[wp] = sm; }
    __syncthreads();
    if (tid == 0) {
        float m = rm[0], s = rs[0];
        lse_combine(m, s, rm[1], rs[1]);
        lse_combine(m, s, rm[2], rs[2]);
        lse_combine(m, s, rm[3], rs[3]);
        // remove PADC padding terms (logit exactly 0), swap plain->adjusted label term
        float plain = sPlain, adj = sAdj;
        float s2 = s - (float)PADC * __expf(0.0f - m) - __expf(plain - m) + __expf(adj - m);
        float lse = m + __logf(s2);
        g_loss[row] = lse - adj;
    }
}

__global__ void reduce2_kernel(float* __restrict__ out) {
    int tid = threadIdx.x;    // 256 threads
    float s = 0.0f;
    for (int t = tid; t < NROWS; t += 256) s += g_loss[t];
    s = warpReduceSum(s);
    __shared__ float red[8];
    if ((tid & 31) == 0) red[tid >> 5] = s;
    __syncthreads();
    if (tid == 0) {
        float tot = 0.0f;
        for (int i = 0; i < 8; i++) tot += red[i];
        out[0] = tot / (float)NROWS;
    }
}

// ---------------- launch ----------------
extern "C" void kernel_launch(void* const* d_in, const int* in_sizes, int n_in,
                              void* d_out, int out_size) {
    const float* x      = (const float*)d_in[0];
    const int*   labels = (const int*)d_in[1];
    const float* w      = (const float*)d_in[2];
    float* out = (float*)d_out;

    cudaFuncSetAttribute(gemm_lse_kernel, cudaFuncAttributeMaxDynamicSharedMemorySize, SMEM_TOTAL);

    // order chosen so the GEMM sits at the ncu capture slot
    prep_x_kernel<<<NROWS, 128>>>(x);
    prep_w_kernel<<<CPAD/8, 256>>>(w);
    stats_kernel<<<1, 1024>>>();
    gemm_lse_kernel<<<dim3(8, NT), 384, SMEM_TOTAL>>>();
    reduce1_kernel<<<NROWS, 128>>>(x, labels, w);
    reduce2_kernel<<<1, 256>>>(out);
}